// round 7
// baseline (speedup 1.0000x reference)
#include <cuda_runtime.h>
#include <cuda_fp16.h>
#include <cstdint>

#define CD 768
#define ND 4096
#define BB 8

using fp16 = __half;

// ---------------------------------------------------------------------------
// Device scratch (module-load allocated; no runtime allocs)
// ---------------------------------------------------------------------------
__device__ fp16 g_x1n_hi[(size_t)BB * ND * CD];  // x1 natural [b][n][c]
__device__ fp16 g_x1n_lo[(size_t)BB * ND * CD];
__device__ fp16 g_x2n_hi[(size_t)BB * ND * CD];  // x2 natural [b][n][c]
__device__ fp16 g_x2n_lo[(size_t)BB * ND * CD];
__device__ float g_attn[(size_t)BB * CD * CD];   // fp32 logits
__device__ fp16 g_at_hi[(size_t)BB * CD * CD];   // softmaxed attn (fp16)

__device__ __constant__ float kScale = 0.10206207261596577f;  // (768/8)^-0.5

// ---------------------------------------------------------------------------
// PTX helpers
// ---------------------------------------------------------------------------
__device__ __forceinline__ uint32_t smem_u32(const void* p) {
    uint32_t a;
    asm("{ .reg .u64 t; cvta.to.shared.u64 t, %1; cvt.u32.u64 %0, t; }" : "=r"(a) : "l"(p));
    return a;
}

__device__ __forceinline__ void cp_async16(uint32_t saddr, const void* gaddr) {
    asm volatile("cp.async.cg.shared.global [%0], [%1], 16;" :: "r"(saddr), "l"(gaddr));
}
#define CP_COMMIT() asm volatile("cp.async.commit_group;" ::: "memory")
#define CP_WAIT(n)  asm volatile("cp.async.wait_group %0;" :: "n"(n) : "memory")

__device__ __forceinline__ void ldsm4(uint32_t& r0, uint32_t& r1, uint32_t& r2,
                                      uint32_t& r3, uint32_t addr) {
    asm volatile("ldmatrix.sync.aligned.m8n8.x4.shared.b16 {%0,%1,%2,%3}, [%4];"
                 : "=r"(r0), "=r"(r1), "=r"(r2), "=r"(r3) : "r"(addr));
}
__device__ __forceinline__ void ldsm4t(uint32_t& r0, uint32_t& r1, uint32_t& r2,
                                       uint32_t& r3, uint32_t addr) {
    asm volatile("ldmatrix.sync.aligned.m8n8.x4.trans.shared.b16 {%0,%1,%2,%3}, [%4];"
                 : "=r"(r0), "=r"(r1), "=r"(r2), "=r"(r3) : "r"(addr));
}

__device__ __forceinline__ void mma_f16(float* c, const uint32_t* a, const uint32_t* b) {
    asm volatile(
        "mma.sync.aligned.m16n8k16.row.col.f32.f16.f16.f32 "
        "{%0,%1,%2,%3}, {%4,%5,%6,%7}, {%8,%9}, {%0,%1,%2,%3};"
        : "+f"(c[0]), "+f"(c[1]), "+f"(c[2]), "+f"(c[3])
        : "r"(a[0]), "r"(a[1]), "r"(a[2]), "r"(a[3]), "r"(b[0]), "r"(b[1]));
}

// ---------------------------------------------------------------------------
// Streaming fp16 split: 8 floats/thread, 16B fp16 stores
// ---------------------------------------------------------------------------
__global__ __launch_bounds__(256) void nsplit_kernel(const float* __restrict__ src,
                                                     fp16* __restrict__ dh,
                                                     fp16* __restrict__ dl) {
    size_t i = ((size_t)blockIdx.x * 256 + threadIdx.x) * 8;
    float4 v0 = *(const float4*)(src + i);
    float4 v1 = *(const float4*)(src + i + 4);
    float f[8] = {v0.x, v0.y, v0.z, v0.w, v1.x, v1.y, v1.z, v1.w};
    fp16 h[8], l[8];
#pragma unroll
    for (int j = 0; j < 8; j++) {
        h[j] = __float2half_rn(f[j]);
        l[j] = __float2half_rn(f[j] - __half2float(h[j]));
    }
    *(uint4*)(dh + i) = *(uint4*)h;
    *(uint4*)(dl + i) = *(uint4*)l;
}

// ---------------------------------------------------------------------------
// Softmax over g_attn rows -> fp16 attn
// ---------------------------------------------------------------------------
__global__ __launch_bounds__(256) void softmax_kernel() {
    const size_t ro = (size_t)blockIdx.x * CD;
    float* p = g_attn + ro;
    const int tid = threadIdx.x;

    float v0 = p[tid], v1 = p[tid + 256], v2 = p[tid + 512];

    float m = fmaxf(fmaxf(v0, v1), v2);
#pragma unroll
    for (int o = 16; o > 0; o >>= 1) m = fmaxf(m, __shfl_xor_sync(0xffffffffu, m, o));

    __shared__ float sm[8], ss[8];
    if ((tid & 31) == 0) sm[tid >> 5] = m;
    __syncthreads();
    float bm = sm[0];
#pragma unroll
    for (int i = 1; i < 8; i++) bm = fmaxf(bm, sm[i]);

    float e0 = __expf(v0 - bm), e1 = __expf(v1 - bm), e2 = __expf(v2 - bm);
    float s = e0 + e1 + e2;
#pragma unroll
    for (int o = 16; o > 0; o >>= 1) s += __shfl_xor_sync(0xffffffffu, s, o);
    if ((tid & 31) == 0) ss[tid >> 5] = s;
    __syncthreads();
    float bs = 0.f;
#pragma unroll
    for (int i = 0; i < 8; i++) bs += ss[i];

    float inv = 1.0f / bs;
    g_at_hi[ro + tid]       = __float2half_rn(e0 * inv);
    g_at_hi[ro + tid + 256] = __float2half_rn(e1 * inv);
    g_at_hi[ro + tid + 512] = __float2half_rn(e2 * inv);
}

// ---------------------------------------------------------------------------
// GEMM1 (logits): attn[m][n] = scale * sum_k x1[k][m]*x2[k][n], k = seq dim.
// Natural [n][c] operands, ldmatrix.trans fragments.
// CTA tile 128x256, 512 threads (16 warps as 2x8, warp tile 64x32),
// BK=32, 3-stage cp.async, ONE barrier per chunk, 3-term fp16 split.
// ---------------------------------------------------------------------------
static constexpr int ROW2A = 272;             // 128 m * 2B + 16 pad
static constexpr int ROW2B = 528;             // 256 n * 2B + 16 pad
static constexpr int TENA = 32 * ROW2A;       // 8704
static constexpr int TENB = 32 * ROW2B;       // 16896
static constexpr int OFF_AL = TENA;           // 8704
static constexpr int OFF_BH = 2 * TENA;       // 17408
static constexpr int OFF_BL = 2 * TENA + TENB;
static constexpr int STG1 = 2 * TENA + 2 * TENB;  // 51200
static constexpr int SM1 = 3 * STG1;              // 153600

__global__ __launch_bounds__(512) void gemm1_kernel() {
    extern __shared__ char smc[];
    const uint32_t smb = smem_u32(smc);
    const int tid = threadIdx.x;
    const int wid = tid >> 5, lane = tid & 31;
    const int wm = wid >> 3, wn = wid & 7;    // 2 x 8 warps
    const int b = blockIdx.z;
    const int m0 = blockIdx.y * 128;
    const int n0 = blockIdx.x * 256;

    const fp16* pAh = g_x1n_hi + (size_t)b * ND * CD + m0;
    const fp16* pAl = g_x1n_lo + (size_t)b * ND * CD + m0;
    const fp16* pBh = g_x2n_hi + (size_t)b * ND * CD + n0;
    const fp16* pBl = g_x2n_lo + (size_t)b * ND * CD + n0;
    float* Cp = g_attn + (size_t)b * CD * CD;

    // A: 512 chunks per tensor (1/thread); B: 1024 per tensor (2/thread)
    const int a_row = tid >> 4, a_seg = tid & 15;
    auto issue = [&](int c, int buf) {
        const int k0 = c * 32;
        const uint32_t sb = smb + buf * STG1;
        {
            const uint32_t so = (uint32_t)a_row * ROW2A + a_seg * 16;
            const size_t go = (size_t)(k0 + a_row) * CD + a_seg * 8;
            cp_async16(sb + so, pAh + go);
            cp_async16(sb + OFF_AL + so, pAl + go);
        }
#pragma unroll
        for (int h = 0; h < 2; h++) {
            const int idx = tid + h * 512;
            const int row = idx >> 5, seg = idx & 31;
            const uint32_t so = (uint32_t)row * ROW2B + seg * 16;
            const size_t go = (size_t)(k0 + row) * CD + seg * 8;
            cp_async16(sb + OFF_BH + so, pBh + go);
            cp_async16(sb + OFF_BL + so, pBl + go);
        }
        CP_COMMIT();
    };

    float acc[4][4][4] = {};
    constexpr int NC = ND / 32;  // 128

    issue(0, 0);
    issue(1, 1);

    // trans-ldmatrix lane addressing
    const int a_kr = ((lane >> 4) << 3) + (lane & 7);
    const int a_mc = (lane >> 3) & 1;
    const int b_kr = (((lane >> 3) & 1) << 3) + (lane & 7);
    const int b_nc = lane >> 4;

    int buf = 0;
    for (int c = 0; c < NC; c++) {
        CP_WAIT(1);
        __syncthreads();
        if (c + 2 < NC) {
            int nb = buf + 2; if (nb >= 3) nb -= 3;
            issue(c + 2, nb);
        }

        const uint32_t sA = smb + buf * STG1;
        const uint32_t sB = sA + OFF_BH;

#pragma unroll
        for (int ks = 0; ks < 2; ks++) {
            uint32_t ah[4][4], al[4][4], bh[2][4], bl[2][4];
            const uint32_t akro = (uint32_t)(ks * 16 + a_kr) * ROW2A;
            const uint32_t bkro = (uint32_t)(ks * 16 + b_kr) * ROW2B;
#pragma unroll
            for (int mt = 0; mt < 4; mt++) {
                uint32_t addr = sA + akro + (uint32_t)(wm * 128 + mt * 32 + a_mc * 16);
                ldsm4t(ah[mt][0], ah[mt][1], ah[mt][2], ah[mt][3], addr);
                ldsm4t(al[mt][0], al[mt][1], al[mt][2], al[mt][3], addr + OFF_AL);
            }
#pragma unroll
            for (int np = 0; np < 2; np++) {
                uint32_t addr = sB + bkro + (uint32_t)(wn * 64 + np * 32 + b_nc * 16);
                ldsm4t(bh[np][0], bh[np][1], bh[np][2], bh[np][3], addr);
                ldsm4t(bl[np][0], bl[np][1], bl[np][2], bl[np][3], addr + TENB);
            }
#pragma unroll
            for (int mt = 0; mt < 4; mt++)
#pragma unroll
                for (int nt = 0; nt < 4; nt++) {
                    const uint32_t* bph = &bh[nt >> 1][(nt & 1) * 2];
                    const uint32_t* bpl = &bl[nt >> 1][(nt & 1) * 2];
                    mma_f16(acc[mt][nt], ah[mt], bph);
                    mma_f16(acc[mt][nt], ah[mt], bpl);
                    mma_f16(acc[mt][nt], al[mt], bph);
                }
        }
        buf++; if (buf == 3) buf = 0;
    }

    const int er = lane >> 2, ec = (lane & 3) * 2;
#pragma unroll
    for (int mt = 0; mt < 4; mt++) {
#pragma unroll
        for (int nt = 0; nt < 4; nt++) {
            float* a4 = acc[mt][nt];
            const int row = m0 + wm * 64 + mt * 16 + er;
            const int col = n0 + wn * 32 + nt * 8 + ec;
            *(float2*)(Cp + (size_t)row * CD + col) =
                make_float2(a4[0] * kScale, a4[1] * kScale);
            *(float2*)(Cp + (size_t)(row + 8) * CD + col) =
                make_float2(a4[2] * kScale, a4[3] * kScale);
        }
    }
}

// ---------------------------------------------------------------------------
// GEMM2 (out): out[m][n] = sum_k attn[m][k]*x2[n][k], k = channel (768).
// K-contiguous, non-trans ldmatrix. 2-term (A fp16, B hi/lo).
// CTA tile 128x256, 512 threads (16 warps as 2x8), BK=32, 3-stage,
// one barrier per chunk. 80B-padded rows.
// ---------------------------------------------------------------------------
static constexpr int ROWB = 80;
static constexpr int TA2 = 128 * ROWB;        // 10240 (Ah: 128 m-rows)
static constexpr int TB2 = 256 * ROWB;        // 20480 (B: 256 n-rows)
static constexpr int OFF2_BH = TA2;
static constexpr int OFF2_BL = TA2 + TB2;
static constexpr int STG2 = TA2 + 2 * TB2;    // 51200
static constexpr int SM2 = 3 * STG2;          // 153600

__global__ __launch_bounds__(512) void gemm2_kernel(float* __restrict__ Cout) {
    extern __shared__ char smc[];
    const uint32_t smb = smem_u32(smc);
    const int tid = threadIdx.x;
    const int wid = tid >> 5, lane = tid & 31;
    const int wm = wid >> 3, wn = wid & 7;
    const int b = blockIdx.z;
    const int m0 = blockIdx.y * 128;
    const int n0 = blockIdx.x * 256;

    const fp16* pAh = g_at_hi + (size_t)b * CD * CD + (size_t)m0 * CD;
    const fp16* pBh = g_x2n_hi + (size_t)b * ND * CD + (size_t)n0 * CD;
    const fp16* pBl = g_x2n_lo + (size_t)b * ND * CD + (size_t)n0 * CD;
    float* Cp = Cout + (size_t)b * CD * ND;

    // A: 512 chunks (1/thread); B: 1024 per tensor (2/thread)
    const int a_row = tid >> 2, a_seg = tid & 3;
    auto issue = [&](int c, int buf) {
        const int k0 = c * 32;
        const uint32_t sb = smb + buf * STG2;
        cp_async16(sb + (uint32_t)a_row * ROWB + a_seg * 16,
                   pAh + (size_t)a_row * CD + k0 + a_seg * 8);
#pragma unroll
        for (int h = 0; h < 2; h++) {
            const int idx = tid + h * 512;
            const int row = idx >> 2, seg = idx & 3;
            const uint32_t so = (uint32_t)row * ROWB + seg * 16;
            const size_t go = (size_t)row * CD + k0 + seg * 8;
            cp_async16(sb + OFF2_BH + so, pBh + go);
            cp_async16(sb + OFF2_BL + so, pBl + go);
        }
        CP_COMMIT();
    };

    float acc[4][4][4] = {};
    constexpr int NC = CD / 32;  // 24

    issue(0, 0);
    issue(1, 1);

    const int a_r = lane & 15, a_h = lane >> 4;
    const int b_r = (lane & 7) + ((lane >> 4) << 3);
    const int b_h = (lane >> 3) & 1;

    int buf = 0;
    for (int c = 0; c < NC; c++) {
        CP_WAIT(1);
        __syncthreads();
        if (c + 2 < NC) {
            int nb = buf + 2; if (nb >= 3) nb -= 3;
            issue(c + 2, nb);
        }

        const uint32_t sA = smb + buf * STG2;
        const uint32_t sB = sA + OFF2_BH;

#pragma unroll
        for (int ks = 0; ks < 2; ks++) {
            const uint32_t kso = ks * 32;
            uint32_t ah[4][4], bh[2][4], bl[2][4];
#pragma unroll
            for (int mt = 0; mt < 4; mt++) {
                uint32_t addr = sA + (uint32_t)(wm * 64 + mt * 16 + a_r) * ROWB + kso + a_h * 16;
                ldsm4(ah[mt][0], ah[mt][1], ah[mt][2], ah[mt][3], addr);
            }
#pragma unroll
            for (int np = 0; np < 2; np++) {
                uint32_t addr = sB + (uint32_t)(wn * 32 + np * 16 + b_r) * ROWB + kso + b_h * 16;
                ldsm4(bh[np][0], bh[np][1], bh[np][2], bh[np][3], addr);
                ldsm4(bl[np][0], bl[np][1], bl[np][2], bl[np][3], addr + TB2);
            }
#pragma unroll
            for (int mt = 0; mt < 4; mt++)
#pragma unroll
                for (int nt = 0; nt < 4; nt++) {
                    const uint32_t* bph = &bh[nt >> 1][(nt & 1) * 2];
                    const uint32_t* bpl = &bl[nt >> 1][(nt & 1) * 2];
                    mma_f16(acc[mt][nt], ah[mt], bph);
                    mma_f16(acc[mt][nt], ah[mt], bpl);
                }
        }
        buf++; if (buf == 3) buf = 0;
    }

    const int er = lane >> 2, ec = (lane & 3) * 2;
#pragma unroll
    for (int mt = 0; mt < 4; mt++) {
#pragma unroll
        for (int nt = 0; nt < 4; nt++) {
            float* a4 = acc[mt][nt];
            const int row = m0 + wm * 64 + mt * 16 + er;
            const int col = n0 + wn * 32 + nt * 8 + ec;
            *(float2*)(Cp + (size_t)row * ND + col) = make_float2(a4[0], a4[1]);
            *(float2*)(Cp + (size_t)(row + 8) * ND + col) = make_float2(a4[2], a4[3]);
        }
    }
}

// ---------------------------------------------------------------------------
extern "C" void kernel_launch(void* const* d_in, const int* in_sizes, int n_in,
                              void* d_out, int out_size) {
    const float* x1 = (const float*)d_in[0];
    const float* x2 = (const float*)d_in[1];
    float* out = (float*)d_out;

    cudaFuncSetAttribute(gemm1_kernel,
                         cudaFuncAttributeMaxDynamicSharedMemorySize, SM1);
    cudaFuncSetAttribute(gemm2_kernel,
                         cudaFuncAttributeMaxDynamicSharedMemorySize, SM2);

    fp16 *x1h, *x1l, *x2h, *x2l;
    cudaGetSymbolAddress((void**)&x1h, g_x1n_hi);
    cudaGetSymbolAddress((void**)&x1l, g_x1n_lo);
    cudaGetSymbolAddress((void**)&x2h, g_x2n_hi);
    cudaGetSymbolAddress((void**)&x2l, g_x2n_lo);

    const int nblk = (int)((size_t)BB * ND * CD / 2048);  // 8 floats/thread
    nsplit_kernel<<<nblk, 256>>>(x1, x1h, x1l);
    nsplit_kernel<<<nblk, 256>>>(x2, x2h, x2l);

    dim3 g1(CD / 256, CD / 128, BB);  // 3 x 6 x 8 = 144 CTAs (one wave)
    gemm1_kernel<<<g1, 512, SM1>>>();

    softmax_kernel<<<BB * CD, 256>>>();

    dim3 g2(ND / 256, CD / 128, BB);  // 16 x 6 x 8 = 768 CTAs
    gemm2_kernel<<<g2, 512, SM2>>>(out);
}

// round 8
// speedup vs baseline: 1.0840x; 1.0840x over previous
#include <cuda_runtime.h>
#include <cuda_fp16.h>
#include <cstdint>

#define CD 768
#define ND 4096
#define BB 8

using fp16 = __half;

// ---------------------------------------------------------------------------
// Device scratch (module-load allocated; no runtime allocs)
// ---------------------------------------------------------------------------
__device__ fp16 g_x1n_hi[(size_t)BB * ND * CD];  // x1 natural [b][n][c]
__device__ fp16 g_x1n_lo[(size_t)BB * ND * CD];
__device__ fp16 g_x2n_hi[(size_t)BB * ND * CD];  // x2 natural [b][n][c]
__device__ fp16 g_x2n_lo[(size_t)BB * ND * CD];
__device__ float g_attn[(size_t)BB * CD * CD];   // fp32 logits
__device__ fp16 g_at_hi[(size_t)BB * CD * CD];   // softmaxed attn (fp16)

__device__ __constant__ float kScale = 0.10206207261596577f;  // (768/8)^-0.5

// ---------------------------------------------------------------------------
// PTX helpers
// ---------------------------------------------------------------------------
__device__ __forceinline__ uint32_t smem_u32(const void* p) {
    uint32_t a;
    asm("{ .reg .u64 t; cvta.to.shared.u64 t, %1; cvt.u32.u64 %0, t; }" : "=r"(a) : "l"(p));
    return a;
}

__device__ __forceinline__ void cp_async16(uint32_t saddr, const void* gaddr) {
    asm volatile("cp.async.cg.shared.global [%0], [%1], 16;" :: "r"(saddr), "l"(gaddr));
}
#define CP_COMMIT() asm volatile("cp.async.commit_group;" ::: "memory")
#define CP_WAIT(n)  asm volatile("cp.async.wait_group %0;" :: "n"(n) : "memory")

__device__ __forceinline__ void ldsm4(uint32_t& r0, uint32_t& r1, uint32_t& r2,
                                      uint32_t& r3, uint32_t addr) {
    asm volatile("ldmatrix.sync.aligned.m8n8.x4.shared.b16 {%0,%1,%2,%3}, [%4];"
                 : "=r"(r0), "=r"(r1), "=r"(r2), "=r"(r3) : "r"(addr));
}
__device__ __forceinline__ void ldsm4t(uint32_t& r0, uint32_t& r1, uint32_t& r2,
                                       uint32_t& r3, uint32_t addr) {
    asm volatile("ldmatrix.sync.aligned.m8n8.x4.trans.shared.b16 {%0,%1,%2,%3}, [%4];"
                 : "=r"(r0), "=r"(r1), "=r"(r2), "=r"(r3) : "r"(addr));
}

__device__ __forceinline__ void mma_f16(float* c, const uint32_t* a, const uint32_t* b) {
    asm volatile(
        "mma.sync.aligned.m16n8k16.row.col.f32.f16.f16.f32 "
        "{%0,%1,%2,%3}, {%4,%5,%6,%7}, {%8,%9}, {%0,%1,%2,%3};"
        : "+f"(c[0]), "+f"(c[1]), "+f"(c[2]), "+f"(c[3])
        : "r"(a[0]), "r"(a[1]), "r"(a[2]), "r"(a[3]), "r"(b[0]), "r"(b[1]));
}

// ---------------------------------------------------------------------------
// Streaming fp16 split: 8 floats/thread, 16B fp16 stores
// ---------------------------------------------------------------------------
__global__ __launch_bounds__(256) void nsplit_kernel(const float* __restrict__ src,
                                                     fp16* __restrict__ dh,
                                                     fp16* __restrict__ dl) {
    size_t i = ((size_t)blockIdx.x * 256 + threadIdx.x) * 8;
    float4 v0 = *(const float4*)(src + i);
    float4 v1 = *(const float4*)(src + i + 4);
    float f[8] = {v0.x, v0.y, v0.z, v0.w, v1.x, v1.y, v1.z, v1.w};
    fp16 h[8], l[8];
#pragma unroll
    for (int j = 0; j < 8; j++) {
        h[j] = __float2half_rn(f[j]);
        l[j] = __float2half_rn(f[j] - __half2float(h[j]));
    }
    *(uint4*)(dh + i) = *(uint4*)h;
    *(uint4*)(dl + i) = *(uint4*)l;
}

// ---------------------------------------------------------------------------
// Softmax over g_attn rows -> fp16 attn
// ---------------------------------------------------------------------------
__global__ __launch_bounds__(256) void softmax_kernel() {
    const size_t ro = (size_t)blockIdx.x * CD;
    float* p = g_attn + ro;
    const int tid = threadIdx.x;

    float v0 = p[tid], v1 = p[tid + 256], v2 = p[tid + 512];

    float m = fmaxf(fmaxf(v0, v1), v2);
#pragma unroll
    for (int o = 16; o > 0; o >>= 1) m = fmaxf(m, __shfl_xor_sync(0xffffffffu, m, o));

    __shared__ float sm[8], ss[8];
    if ((tid & 31) == 0) sm[tid >> 5] = m;
    __syncthreads();
    float bm = sm[0];
#pragma unroll
    for (int i = 1; i < 8; i++) bm = fmaxf(bm, sm[i]);

    float e0 = __expf(v0 - bm), e1 = __expf(v1 - bm), e2 = __expf(v2 - bm);
    float s = e0 + e1 + e2;
#pragma unroll
    for (int o = 16; o > 0; o >>= 1) s += __shfl_xor_sync(0xffffffffu, s, o);
    if ((tid & 31) == 0) ss[tid >> 5] = s;
    __syncthreads();
    float bs = 0.f;
#pragma unroll
    for (int i = 0; i < 8; i++) bs += ss[i];

    float inv = 1.0f / bs;
    g_at_hi[ro + tid]       = __float2half_rn(e0 * inv);
    g_at_hi[ro + tid + 256] = __float2half_rn(e1 * inv);
    g_at_hi[ro + tid + 512] = __float2half_rn(e2 * inv);
}

// ---------------------------------------------------------------------------
// GEMM1 (logits): attn[m][n] = scale * sum_k x1[k][m]*x2[k][n], k = seq dim.
// Natural [n][c] operands, ldmatrix.trans fragments.
// CTA 128x128, 256 threads (8 warps, 64x32 warp tile), BK=32, 3-stage,
// ONE barrier per chunk, 3-term fp16 split. 2 CTAs/SM.
// ---------------------------------------------------------------------------
static constexpr int ROW2 = 272;
static constexpr int TEN2 = 32 * ROW2;      // 8704
static constexpr int STG2 = 4 * TEN2;       // 34816
static constexpr int SM1 = 3 * STG2;        // 104448

__global__ __launch_bounds__(256) void gemm1_kernel() {
    extern __shared__ char smc[];
    const uint32_t smb = smem_u32(smc);
    const int tid = threadIdx.x;
    const int wid = tid >> 5, lane = tid & 31;
    const int wm = wid >> 2, wn = wid & 3;
    const int b = blockIdx.z;
    const int m0 = blockIdx.y * 128;
    const int n0 = blockIdx.x * 128;

    const fp16* pAh = g_x1n_hi + (size_t)b * ND * CD + m0;
    const fp16* pAl = g_x1n_lo + (size_t)b * ND * CD + m0;
    const fp16* pBh = g_x2n_hi + (size_t)b * ND * CD + n0;
    const fp16* pBl = g_x2n_lo + (size_t)b * ND * CD + n0;
    float* Cp = g_attn + (size_t)b * CD * CD;

    auto issue = [&](int c, int buf) {
        const int k0 = c * 32;
        const uint32_t sb = smb + buf * STG2;
#pragma unroll
        for (int h = 0; h < 2; h++) {
            const int idx = tid + h * 256;
            const int row = idx >> 4, seg = idx & 15;
            const uint32_t so = (uint32_t)row * ROW2 + seg * 16;
            const size_t go = (size_t)(k0 + row) * CD + seg * 8;
            cp_async16(sb + so, pAh + go);
            cp_async16(sb + TEN2 + so, pAl + go);
            cp_async16(sb + 2 * TEN2 + so, pBh + go);
            cp_async16(sb + 3 * TEN2 + so, pBl + go);
        }
        CP_COMMIT();
    };

    float acc[4][4][4] = {};
    constexpr int NC = ND / 32;  // 128

    issue(0, 0);
    issue(1, 1);

    const int a_kr = ((lane >> 4) << 3) + (lane & 7);
    const int a_mc = (lane >> 3) & 1;
    const int b_kr = (((lane >> 3) & 1) << 3) + (lane & 7);
    const int b_nc = lane >> 4;

    int buf = 0;
    for (int c = 0; c < NC; c++) {
        CP_WAIT(1);
        __syncthreads();
        if (c + 2 < NC) {
            int nb = buf + 2; if (nb >= 3) nb -= 3;
            issue(c + 2, nb);
        }

        const uint32_t sA = smb + buf * STG2;
        const uint32_t sB = sA + 2 * TEN2;

#pragma unroll
        for (int ks = 0; ks < 2; ks++) {
            uint32_t ah[4][4], al[4][4], bh[2][4], bl[2][4];
            const uint32_t akro = (uint32_t)(ks * 16 + a_kr) * ROW2;
            const uint32_t bkro = (uint32_t)(ks * 16 + b_kr) * ROW2;
#pragma unroll
            for (int mt = 0; mt < 4; mt++) {
                uint32_t addr = sA + akro + (uint32_t)(wm * 128 + mt * 32 + a_mc * 16);
                ldsm4t(ah[mt][0], ah[mt][1], ah[mt][2], ah[mt][3], addr);
                ldsm4t(al[mt][0], al[mt][1], al[mt][2], al[mt][3], addr + TEN2);
            }
#pragma unroll
            for (int np = 0; np < 2; np++) {
                uint32_t addr = sB + bkro + (uint32_t)(wn * 64 + np * 32 + b_nc * 16);
                ldsm4t(bh[np][0], bh[np][1], bh[np][2], bh[np][3], addr);
                ldsm4t(bl[np][0], bl[np][1], bl[np][2], bl[np][3], addr + TEN2);
            }
#pragma unroll
            for (int mt = 0; mt < 4; mt++)
#pragma unroll
                for (int nt = 0; nt < 4; nt++) {
                    const uint32_t* bph = &bh[nt >> 1][(nt & 1) * 2];
                    const uint32_t* bpl = &bl[nt >> 1][(nt & 1) * 2];
                    mma_f16(acc[mt][nt], ah[mt], bph);
                    mma_f16(acc[mt][nt], ah[mt], bpl);
                    mma_f16(acc[mt][nt], al[mt], bph);
                }
        }
        buf++; if (buf == 3) buf = 0;
    }

    const int er = lane >> 2, ec = (lane & 3) * 2;
#pragma unroll
    for (int mt = 0; mt < 4; mt++) {
#pragma unroll
        for (int nt = 0; nt < 4; nt++) {
            float* a4 = acc[mt][nt];
            const int row = m0 + wm * 64 + mt * 16 + er;
            const int col = n0 + wn * 32 + nt * 8 + ec;
            *(float2*)(Cp + (size_t)row * CD + col) =
                make_float2(a4[0] * kScale, a4[1] * kScale);
            *(float2*)(Cp + (size_t)(row + 8) * CD + col) =
                make_float2(a4[2] * kScale, a4[3] * kScale);
        }
    }
}

// ---------------------------------------------------------------------------
// GEMM2 (out): out[m][n] = sum_k attn[m][k]*x2[n][k], k = channel (768).
// K-contiguous, non-trans ldmatrix. 2-term (A fp16, B hi/lo).
// CTA 128x128, 256 threads, BK=32, 3-stage, one barrier per chunk.
// 80B-padded rows. 2 CTAs/SM.
// ---------------------------------------------------------------------------
static constexpr int ROWB = 80;
static constexpr int TEN = 128 * ROWB;      // 10240
static constexpr int STG3 = 3 * TEN;        // 30720 (Ah, Bh, Bl)
static constexpr int SM2 = 3 * STG3;        // 92160

__global__ __launch_bounds__(256) void gemm2_kernel(float* __restrict__ Cout) {
    extern __shared__ char smc[];
    const uint32_t smb = smem_u32(smc);
    const int tid = threadIdx.x;
    const int wid = tid >> 5, lane = tid & 31;
    const int wm = wid >> 2, wn = wid & 3;
    const int b = blockIdx.z;
    const int m0 = blockIdx.y * 128;
    const int n0 = blockIdx.x * 128;

    const fp16* pAh = g_at_hi + (size_t)b * CD * CD + (size_t)m0 * CD;
    const fp16* pBh = g_x2n_hi + (size_t)b * ND * CD + (size_t)n0 * CD;
    const fp16* pBl = g_x2n_lo + (size_t)b * ND * CD + (size_t)n0 * CD;
    float* Cp = Cout + (size_t)b * CD * ND;

    const int lrow = tid >> 2;
    const int lseg = tid & 3;

    auto issue = [&](int c, int buf) {
        const int k0 = c * 32;
        const uint32_t sb = smb + buf * STG3;
#pragma unroll
        for (int h = 0; h < 2; h++) {
            const int row = lrow + h * 64;
            const uint32_t so = (uint32_t)row * ROWB + lseg * 16;
            const size_t go = (size_t)row * CD + k0 + lseg * 8;
            cp_async16(sb + so, pAh + go);
            cp_async16(sb + TEN + so, pBh + go);
            cp_async16(sb + 2 * TEN + so, pBl + go);
        }
        CP_COMMIT();
    };

    float acc[4][4][4] = {};
    constexpr int NC = CD / 32;  // 24

    issue(0, 0);
    issue(1, 1);

    const int a_r = lane & 15, a_h = lane >> 4;
    const int b_r = (lane & 7) + ((lane >> 4) << 3);
    const int b_h = (lane >> 3) & 1;

    int buf = 0;
    for (int c = 0; c < NC; c++) {
        CP_WAIT(1);
        __syncthreads();
        if (c + 2 < NC) {
            int nb = buf + 2; if (nb >= 3) nb -= 3;
            issue(c + 2, nb);
        }

        const uint32_t sA = smb + buf * STG3;
        const uint32_t sB = sA + TEN;

#pragma unroll
        for (int ks = 0; ks < 2; ks++) {
            const uint32_t kso = ks * 32;
            uint32_t ah[4][4], bh[2][4], bl[2][4];
#pragma unroll
            for (int mt = 0; mt < 4; mt++) {
                uint32_t addr = sA + (uint32_t)(wm * 64 + mt * 16 + a_r) * ROWB + kso + a_h * 16;
                ldsm4(ah[mt][0], ah[mt][1], ah[mt][2], ah[mt][3], addr);
            }
#pragma unroll
            for (int np = 0; np < 2; np++) {
                uint32_t addr = sB + (uint32_t)(wn * 32 + np * 16 + b_r) * ROWB + kso + b_h * 16;
                ldsm4(bh[np][0], bh[np][1], bh[np][2], bh[np][3], addr);
                ldsm4(bl[np][0], bl[np][1], bl[np][2], bl[np][3], addr + TEN);
            }
#pragma unroll
            for (int mt = 0; mt < 4; mt++)
#pragma unroll
                for (int nt = 0; nt < 4; nt++) {
                    const uint32_t* bph = &bh[nt >> 1][(nt & 1) * 2];
                    const uint32_t* bpl = &bl[nt >> 1][(nt & 1) * 2];
                    mma_f16(acc[mt][nt], ah[mt], bph);
                    mma_f16(acc[mt][nt], ah[mt], bpl);
                }
        }
        buf++; if (buf == 3) buf = 0;
    }

    const int er = lane >> 2, ec = (lane & 3) * 2;
#pragma unroll
    for (int mt = 0; mt < 4; mt++) {
#pragma unroll
        for (int nt = 0; nt < 4; nt++) {
            float* a4 = acc[mt][nt];
            const int row = m0 + wm * 64 + mt * 16 + er;
            const int col = n0 + wn * 32 + nt * 8 + ec;
            *(float2*)(Cp + (size_t)row * ND + col) = make_float2(a4[0], a4[1]);
            *(float2*)(Cp + (size_t)(row + 8) * ND + col) = make_float2(a4[2], a4[3]);
        }
    }
}

// ---------------------------------------------------------------------------
extern "C" void kernel_launch(void* const* d_in, const int* in_sizes, int n_in,
                              void* d_out, int out_size) {
    const float* x1 = (const float*)d_in[0];
    const float* x2 = (const float*)d_in[1];
    float* out = (float*)d_out;

    cudaFuncSetAttribute(gemm1_kernel,
                         cudaFuncAttributeMaxDynamicSharedMemorySize, SM1);
    cudaFuncSetAttribute(gemm2_kernel,
                         cudaFuncAttributeMaxDynamicSharedMemorySize, SM2);

    fp16 *x1h, *x1l, *x2h, *x2l;
    cudaGetSymbolAddress((void**)&x1h, g_x1n_hi);
    cudaGetSymbolAddress((void**)&x1l, g_x1n_lo);
    cudaGetSymbolAddress((void**)&x2h, g_x2n_hi);
    cudaGetSymbolAddress((void**)&x2l, g_x2n_lo);

    const int nblk = (int)((size_t)BB * ND * CD / 2048);  // 8 floats/thread
    nsplit_kernel<<<nblk, 256>>>(x1, x1h, x1l);
    nsplit_kernel<<<nblk, 256>>>(x2, x2h, x2l);

    dim3 g1(CD / 128, CD / 128, BB);  // 6 x 6 x 8 = 288 CTAs
    gemm1_kernel<<<g1, 256, SM1>>>();

    softmax_kernel<<<BB * CD, 256>>>();

    dim3 g2(ND / 128, CD / 128, BB);  // 32 x 6 x 8 = 768 CTAs
    gemm2_kernel<<<g2, 256, SM2>>>(out);
}